// round 12
// baseline (speedup 1.0000x reference)
#include <cuda_runtime.h>
#include <cuda_fp16.h>
#include <cstdint>

#define N_TOKENS 8192
#define D_MODEL  1024
#define D_FF     4096
#define N_EXPERTS 8

#define BM 128
#define BN 128
#define BK 64
#define NKSTAGE (D_MODEL / BK)        // 16
#define PIPE 3
#define MAX_TILES 72
#define PAD_ROWS (N_TOKENS + N_EXPERTS * BM)   // 9216
#define NTHREADS 256

// ---------------- scratch ----------------
__device__ int g_top1[N_TOKENS];
__device__ int g_counts[N_EXPERTS];
__device__ int g_cursor[N_EXPERTS];
__device__ int g_offsets[N_EXPERTS];
__device__ int g_order[PAD_ROWS];              // -1 = pad row
__device__ int g_tile_expert[MAX_TILES + 8];
__device__ int g_tile_row[MAX_TILES + 8];
__device__ int g_ntiles;

__device__ __half g_xh[(size_t)PAD_ROWS * D_MODEL];            // grouped+padded, fp16 (pads stay BSS-zero)
__device__ __half g_wh[(size_t)N_EXPERTS * D_MODEL * D_FF];    // W fp16, layout [e][d][f]

// ---------------- helpers ----------------
__device__ __forceinline__ uint32_t smem_u32(const void* p) {
    uint32_t a;
    asm("{ .reg .u64 t; cvta.to.shared.u64 t, %1; cvt.u32.u64 %0, t; }" : "=r"(a) : "l"(p));
    return a;
}
__device__ __forceinline__ void cp16(uint32_t dst, const void* src) {
    asm volatile("cp.async.cg.shared.global [%0], [%1], 16;\n" :: "r"(dst), "l"(src));
}
__device__ __forceinline__ void cp_commit() { asm volatile("cp.async.commit_group;\n" ::: "memory"); }
template <int N> __device__ __forceinline__ void cp_wait() {
    asm volatile("cp.async.wait_group %0;\n" :: "n"(N) : "memory");
}
__device__ __forceinline__ void ldsm4(uint32_t r[4], uint32_t addr) {
    asm volatile("ldmatrix.sync.aligned.m8n8.x4.shared.b16 {%0,%1,%2,%3}, [%4];"
                 : "=r"(r[0]), "=r"(r[1]), "=r"(r[2]), "=r"(r[3]) : "r"(addr));
}
__device__ __forceinline__ void ldsm4t(uint32_t r[4], uint32_t addr) {
    asm volatile("ldmatrix.sync.aligned.m8n8.x4.trans.shared.b16 {%0,%1,%2,%3}, [%4];"
                 : "=r"(r[0]), "=r"(r[1]), "=r"(r[2]), "=r"(r[3]) : "r"(addr));
}
// fp16 MMA, fp32 accumulate
#define MMA(d, a, b0, b1)                                                          \
    asm volatile("mma.sync.aligned.m16n8k16.row.col.f32.f16.f16.f32 "              \
                 "{%0,%1,%2,%3},{%4,%5,%6,%7},{%8,%9},{%0,%1,%2,%3};"              \
                 : "+f"((d)[0]), "+f"((d)[1]), "+f"((d)[2]), "+f"((d)[3])          \
                 : "r"((a)[0]), "r"((a)[1]), "r"((a)[2]), "r"((a)[3]),             \
                   "r"(b0), "r"(b1))

// A tile: 128 rows x 128B (64 fp16), 8x16B chunks, chunk ^= row&7 (proven)
__device__ __forceinline__ uint32_t swzA(int row, int c) {
    return (uint32_t)(row * 128 + ((c ^ (row & 7)) << 4));
}
// B tile: 64 k-rows x 256B (128 fp16), 16x16B chunks, chunk ^= row&7 (proven)
__device__ __forceinline__ uint32_t swzB(int row, int c) {
    return (uint32_t)(row * 256 + ((c ^ (row & 7)) << 4));
}

#define A_OFF 0
#define B_OFF 16384
#define STAGE_BYTES 32768          // A 16K + B 16K
#define SMEM_TOTAL (PIPE * STAGE_BYTES)   // 98304 -> 2 CTAs/SM

// ---------------- fused W convert + state init ----------------
__global__ void k_whalf_init(const float* __restrict__ ew) {
    // init side-band state in the first blocks (independent of W data)
    int gidx = blockIdx.x * blockDim.x + threadIdx.x;
    if (gidx < N_EXPERTS) { g_counts[gidx] = 0; g_cursor[gidx] = 0; }
    if (gidx < PAD_ROWS) g_order[gidx] = -1;

    size_t i = (size_t)gidx * 8;
    float4 v0 = *(const float4*)(ew + i);
    float4 v1 = *(const float4*)(ew + i + 4);
    __half h[8];
    h[0] = __float2half(v0.x); h[1] = __float2half(v0.y);
    h[2] = __float2half(v0.z); h[3] = __float2half(v0.w);
    h[4] = __float2half(v1.x); h[5] = __float2half(v1.y);
    h[6] = __float2half(v1.z); h[7] = __float2half(v1.w);
    *(uint4*)(g_wh + i) = *(uint4*)h;
}

// ---------------- gate (vectorized) ----------------
__global__ void k_gate(const float* __restrict__ x, const float* __restrict__ gw,
                       const float* __restrict__ gb) {
    int warp = (blockIdx.x * blockDim.x + threadIdx.x) >> 5;
    int lane = threadIdx.x & 31;
    if (warp >= N_TOKENS) return;
    const float* xr = x + (size_t)warp * D_MODEL;
    float acc[N_EXPERTS];
#pragma unroll
    for (int e = 0; e < N_EXPERTS; e++) acc[e] = 0.f;
#pragma unroll
    for (int i = 0; i < D_MODEL / 128; i++) {   // 8 iters, float4 per lane
        int d = i * 128 + lane * 4;
        float4 xv = *(const float4*)(xr + d);
        float f[4] = {xv.x, xv.y, xv.z, xv.w};
#pragma unroll
        for (int j = 0; j < 4; j++) {
            const float* g = gw + (size_t)(d + j) * N_EXPERTS;
#pragma unroll
            for (int e = 0; e < N_EXPERTS; e++) acc[e] += f[j] * g[e];
        }
    }
#pragma unroll
    for (int e = 0; e < N_EXPERTS; e++)
#pragma unroll
        for (int off = 16; off; off >>= 1)
            acc[e] += __shfl_xor_sync(0xffffffffu, acc[e], off);
    if (lane == 0) {
        int best = 0;
        float bv = acc[0] + gb[0];
#pragma unroll
        for (int e = 1; e < N_EXPERTS; e++) {
            float v = acc[e] + gb[e];
            if (v > bv) { bv = v; best = e; }   // first max wins == jnp.argmax
        }
        g_top1[warp] = best;
        atomicAdd(&g_counts[best], 1);
    }
}

__global__ void k_scan() {
    int base = 0, nt = 0;
    for (int e = 0; e < N_EXPERTS; e++) {
        g_offsets[e] = base;
        int c = g_counts[e];
        int t = (c + BM - 1) / BM;
        for (int r = 0; r < t; r++) {
            g_tile_expert[nt] = e;
            g_tile_row[nt] = base + r * BM;
            nt++;
        }
        base += t * BM;
    }
    g_ntiles = nt;
}

// ---------------- fused scatter + gather-convert ----------------
// one block per token: thread 0 claims grouped position, all threads convert row
__global__ void k_scatter_convert(const float* __restrict__ x) {
    __shared__ int s_pos;
    int n = blockIdx.x;
    if (threadIdx.x == 0) {
        int e = g_top1[n];
        int pos = g_offsets[e] + atomicAdd(&g_cursor[e], 1);
        g_order[pos] = n;
        s_pos = pos;
    }
    __syncthreads();
    int pos = s_pos;
    int c0 = threadIdx.x * 4;
    float4 v = *(const float4*)(x + (size_t)n * D_MODEL + c0);
    __half h[4];
    h[0] = __float2half(v.x); h[1] = __float2half(v.y);
    h[2] = __float2half(v.z); h[3] = __float2half(v.w);
    *(uint2*)(g_xh + (size_t)pos * D_MODEL + c0) = *(uint2*)h;
}

// ---------------- single-term fp16 grouped GEMM (identical to R11) ----------------
__device__ __forceinline__ void issue_stage(int tid, uint32_t sb, int stage,
                                            int row0, int e, int col0, int k0) {
    uint32_t base = sb + (stage % PIPE) * STAGE_BYTES;
#pragma unroll
    for (int i = 0; i < 4; i++) {
        int idx = tid + i * NTHREADS;
        int row = idx >> 3, c = idx & 7;
        const __half* src = g_xh + (size_t)(row0 + row) * D_MODEL + k0 + c * 8;
        cp16(base + A_OFF + swzA(row, c), src);
    }
#pragma unroll
    for (int i = 0; i < 4; i++) {
        int idx = tid + i * NTHREADS;
        int row = idx >> 4, c = idx & 15;
        const __half* src = g_wh + ((size_t)e * D_MODEL + k0 + row) * D_FF + col0 + c * 8;
        cp16(base + B_OFF + swzB(row, c), src);
    }
    cp_commit();
}

__global__ void __launch_bounds__(NTHREADS, 2)
k_gemm(const float* __restrict__ eb, float* __restrict__ out) {
    int tile = blockIdx.x;
    if (tile >= g_ntiles) return;
    int e = g_tile_expert[tile];
    int row0 = g_tile_row[tile];
    int col0 = blockIdx.y * BN;

    extern __shared__ char smem[];
    __shared__ int s_tok[BM];
    uint32_t sb = smem_u32(smem);
    int tid = threadIdx.x;
    int lane = tid & 31;
    int wid = tid >> 5;      // 8 warps
    int wm = wid & 1;        // 2 M groups (64 rows)
    int wn = wid >> 1;       // 4 N groups (32 cols)

    for (int m = tid; m < BM; m += NTHREADS) s_tok[m] = g_order[row0 + m];

    float acc[4][4][4];
#pragma unroll
    for (int a = 0; a < 4; a++)
#pragma unroll
        for (int b = 0; b < 4; b++)
#pragma unroll
            for (int c = 0; c < 4; c++) acc[a][b][c] = 0.f;

#pragma unroll
    for (int p = 0; p < PIPE - 1; p++) issue_stage(tid, sb, p, row0, e, col0, p * BK);

    int a_row = wm * 64 + (lane & 15);
    int a_cbit = (lane >> 4) & 1;
    int b_krow = lane & 15;
    int b_chalf = lane >> 4;

    for (int s = 0; s < NKSTAGE; s++) {
        cp_wait<PIPE - 2>();
        __syncthreads();
        if (s + PIPE - 1 < NKSTAGE)
            issue_stage(tid, sb, s + PIPE - 1, row0, e, col0, (s + PIPE - 1) * BK);
        else
            cp_commit();   // keep wait_group accounting aligned

        uint32_t base = sb + (s % PIPE) * STAGE_BYTES;
        uint32_t bbase = base + B_OFF;

#pragma unroll
        for (int ks = 0; ks < 4; ks++) {
            uint32_t a[4][4];
#pragma unroll
            for (int mf = 0; mf < 4; mf++)
                ldsm4(a[mf], base + A_OFF + swzA(a_row + mf * 16, ks * 2 + a_cbit));

            int krow = ks * 16 + b_krow;
#pragma unroll
            for (int t = 0; t < 2; t++) {
                int cchunk = wn * 4 + t * 2 + b_chalf;
                uint32_t bh[4];
                ldsm4t(bh, bbase + swzB(krow, cchunk));
#pragma unroll
                for (int mf = 0; mf < 4; mf++) {
                    MMA(acc[mf][t * 2],     a[mf], bh[0], bh[1]);
                    MMA(acc[mf][t * 2 + 1], a[mf], bh[2], bh[3]);
                }
            }
        }
    }
    __syncthreads();

    const float* bias = eb + (size_t)e * D_FF + col0 + wn * 32;
#pragma unroll
    for (int mf = 0; mf < 4; mf++) {
        int r_lo = wm * 64 + mf * 16 + (lane >> 2);
        int t_lo = s_tok[r_lo];
        int t_hi = s_tok[r_lo + 8];
#pragma unroll
        for (int nf = 0; nf < 4; nf++) {
            int cb = nf * 8 + (lane & 3) * 2;
            float b0 = bias[cb], b1 = bias[cb + 1];
            if (t_lo >= 0) {
                float2 v = {acc[mf][nf][0] + b0, acc[mf][nf][1] + b1};
                *(float2*)(out + (size_t)t_lo * D_FF + col0 + wn * 32 + cb) = v;
            }
            if (t_hi >= 0) {
                float2 v = {acc[mf][nf][2] + b0, acc[mf][nf][3] + b1};
                *(float2*)(out + (size_t)t_hi * D_FF + col0 + wn * 32 + cb) = v;
            }
        }
    }
}

extern "C" void kernel_launch(void* const* d_in, const int* in_sizes, int n_in,
                              void* d_out, int out_size) {
    const float* x  = (const float*)d_in[0];
    const float* gw = (const float*)d_in[1];
    const float* gb = (const float*)d_in[2];
    const float* ew = (const float*)d_in[3];
    const float* eb = (const float*)d_in[4];
    float* out = (float*)d_out;

    cudaFuncSetAttribute(k_gemm, cudaFuncAttributeMaxDynamicSharedMemorySize, SMEM_TOTAL);

    k_whalf_init<<<(int)(((size_t)N_EXPERTS * D_MODEL * D_FF) / (256 * 8)), 256>>>(ew);
    k_gate<<<N_TOKENS / 8, 256>>>(x, gw, gb);
    k_scan<<<1, 1>>>();
    k_scatter_convert<<<N_TOKENS, 256>>>(x);
    {
        dim3 g(MAX_TILES, D_FF / BN);
        k_gemm<<<g, NTHREADS, SMEM_TOTAL>>>(eb, out);
    }
}

// round 13
// speedup vs baseline: 1.5800x; 1.5800x over previous
#include <cuda_runtime.h>
#include <cuda_fp16.h>
#include <cstdint>

#define N_TOKENS 8192
#define D_MODEL  1024
#define D_FF     4096
#define N_EXPERTS 8

#define BM 128
#define BN 128
#define BK 64
#define NKSTAGE (D_MODEL / BK)        // 16
#define PIPE 3
#define MAX_TILES 72
#define PAD_ROWS (N_TOKENS + N_EXPERTS * BM)   // 9216
#define NTHREADS 256

// ---------------- scratch ----------------
__device__ int g_top1[N_TOKENS];
__device__ int g_counts[N_EXPERTS];
__device__ int g_cursor[N_EXPERTS];
__device__ int g_offsets[N_EXPERTS];
__device__ int g_order[PAD_ROWS];              // -1 = pad row
__device__ int g_tile_expert[MAX_TILES + 8];
__device__ int g_tile_row[MAX_TILES + 8];
__device__ int g_ntiles;

__device__ __half g_xh[(size_t)PAD_ROWS * D_MODEL];            // grouped+padded, fp16
__device__ __half g_wh[(size_t)N_EXPERTS * D_MODEL * D_FF];    // W fp16, layout [e][d][f]

// ---------------- helpers ----------------
__device__ __forceinline__ uint32_t smem_u32(const void* p) {
    uint32_t a;
    asm("{ .reg .u64 t; cvta.to.shared.u64 t, %1; cvt.u32.u64 %0, t; }" : "=r"(a) : "l"(p));
    return a;
}
__device__ __forceinline__ void cp16(uint32_t dst, const void* src) {
    asm volatile("cp.async.cg.shared.global [%0], [%1], 16;\n" :: "r"(dst), "l"(src));
}
__device__ __forceinline__ void cp_commit() { asm volatile("cp.async.commit_group;\n" ::: "memory"); }
template <int N> __device__ __forceinline__ void cp_wait() {
    asm volatile("cp.async.wait_group %0;\n" :: "n"(N) : "memory");
}
__device__ __forceinline__ void ldsm4(uint32_t r[4], uint32_t addr) {
    asm volatile("ldmatrix.sync.aligned.m8n8.x4.shared.b16 {%0,%1,%2,%3}, [%4];"
                 : "=r"(r[0]), "=r"(r[1]), "=r"(r[2]), "=r"(r[3]) : "r"(addr));
}
__device__ __forceinline__ void ldsm4t(uint32_t r[4], uint32_t addr) {
    asm volatile("ldmatrix.sync.aligned.m8n8.x4.trans.shared.b16 {%0,%1,%2,%3}, [%4];"
                 : "=r"(r[0]), "=r"(r[1]), "=r"(r[2]), "=r"(r[3]) : "r"(addr));
}
// fp16 MMA, fp32 accumulate
#define MMA(d, a, b0, b1)                                                          \
    asm volatile("mma.sync.aligned.m16n8k16.row.col.f32.f16.f16.f32 "              \
                 "{%0,%1,%2,%3},{%4,%5,%6,%7},{%8,%9},{%0,%1,%2,%3};"              \
                 : "+f"((d)[0]), "+f"((d)[1]), "+f"((d)[2]), "+f"((d)[3])          \
                 : "r"((a)[0]), "r"((a)[1]), "r"((a)[2]), "r"((a)[3]),             \
                   "r"(b0), "r"(b1))

// A tile: 128 rows x 128B (64 fp16), 8x16B chunks, chunk ^= row&7 (proven)
__device__ __forceinline__ uint32_t swzA(int row, int c) {
    return (uint32_t)(row * 128 + ((c ^ (row & 7)) << 4));
}
// B tile: 64 k-rows x 256B (128 fp16), 16x16B chunks, chunk ^= row&7 (proven)
__device__ __forceinline__ uint32_t swzB(int row, int c) {
    return (uint32_t)(row * 256 + ((c ^ (row & 7)) << 4));
}

#define A_OFF 0
#define B_OFF 16384
#define STAGE_BYTES 32768          // A 16K + B 16K
#define SMEM_TOTAL (PIPE * STAGE_BYTES)   // 98304 -> 2 CTAs/SM

// ---------------- gate path (R11-proven versions) ----------------
__global__ void k_gate(const float* __restrict__ x, const float* __restrict__ gw,
                       const float* __restrict__ gb) {
    int warp = (blockIdx.x * blockDim.x + threadIdx.x) >> 5;
    int lane = threadIdx.x & 31;
    if (warp >= N_TOKENS) return;
    const float* xr = x + (size_t)warp * D_MODEL;
    float acc[N_EXPERTS];
#pragma unroll
    for (int e = 0; e < N_EXPERTS; e++) acc[e] = 0.f;
#pragma unroll 4
    for (int i = 0; i < D_MODEL / 32; i++) {
        int d = i * 32 + lane;
        float xv = xr[d];
        const float* g = gw + d * N_EXPERTS;
#pragma unroll
        for (int e = 0; e < N_EXPERTS; e++) acc[e] += xv * g[e];
    }
#pragma unroll
    for (int e = 0; e < N_EXPERTS; e++)
#pragma unroll
        for (int off = 16; off; off >>= 1)
            acc[e] += __shfl_xor_sync(0xffffffffu, acc[e], off);
    if (lane == 0) {
        int best = 0;
        float bv = acc[0] + gb[0];
#pragma unroll
        for (int e = 1; e < N_EXPERTS; e++) {
            float v = acc[e] + gb[e];
            if (v > bv) { bv = v; best = e; }   // first max wins == jnp.argmax
        }
        g_top1[warp] = best;
        atomicAdd(&g_counts[best], 1);
    }
}

__global__ void k_scan() {
    int base = 0, nt = 0;
    for (int e = 0; e < N_EXPERTS; e++) {
        g_offsets[e] = base;
        int c = g_counts[e];
        int t = (c + BM - 1) / BM;
        for (int r = 0; r < t; r++) {
            g_tile_expert[nt] = e;
            g_tile_row[nt] = base + r * BM;
            nt++;
        }
        base += t * BM;
    }
    g_ntiles = nt;
}

__global__ void k_scatter() {
    int n = blockIdx.x * blockDim.x + threadIdx.x;
    if (n >= N_TOKENS) return;
    int e = g_top1[n];
    int pos = g_offsets[e] + atomicAdd(&g_cursor[e], 1);
    g_order[pos] = n;
}

// ---------------- conversions ----------------
// gather token rows into grouped/padded order, fp32 -> fp16
__global__ void k_half_x(const float* __restrict__ x) {
    int pos = blockIdx.x;
    int tok = g_order[pos];
    int c0 = threadIdx.x * 4;
    __half h[4];
    if (tok >= 0) {
        float4 v = *(const float4*)(x + (size_t)tok * D_MODEL + c0);
        h[0] = __float2half(v.x); h[1] = __float2half(v.y);
        h[2] = __float2half(v.z); h[3] = __float2half(v.w);
    } else {
        h[0] = h[1] = h[2] = h[3] = __float2half(0.f);
    }
    *(uint2*)(g_xh + (size_t)pos * D_MODEL + c0) = *(uint2*)h;
}

// elementwise W fp32 -> fp16 + fused counter/order init (independent work)
__global__ void k_whalf(const float* __restrict__ ew) {
    int gidx = blockIdx.x * blockDim.x + threadIdx.x;
    if (gidx < N_EXPERTS) { g_counts[gidx] = 0; g_cursor[gidx] = 0; }
    if (gidx < PAD_ROWS) g_order[gidx] = -1;

    size_t i = (size_t)gidx * 8;
    float4 v0 = *(const float4*)(ew + i);
    float4 v1 = *(const float4*)(ew + i + 4);
    __half h[8];
    h[0] = __float2half(v0.x); h[1] = __float2half(v0.y);
    h[2] = __float2half(v0.z); h[3] = __float2half(v0.w);
    h[4] = __float2half(v1.x); h[5] = __float2half(v1.y);
    h[6] = __float2half(v1.z); h[7] = __float2half(v1.w);
    *(uint4*)(g_wh + i) = *(uint4*)h;
}

// ---------------- single-term fp16 grouped GEMM (R11, unchanged) ----------------
__device__ __forceinline__ void issue_stage(int tid, uint32_t sb, int stage,
                                            int row0, int e, int col0, int k0) {
    uint32_t base = sb + (stage % PIPE) * STAGE_BYTES;
#pragma unroll
    for (int i = 0; i < 4; i++) {
        int idx = tid + i * NTHREADS;
        int row = idx >> 3, c = idx & 7;
        const __half* src = g_xh + (size_t)(row0 + row) * D_MODEL + k0 + c * 8;
        cp16(base + A_OFF + swzA(row, c), src);
    }
#pragma unroll
    for (int i = 0; i < 4; i++) {
        int idx = tid + i * NTHREADS;
        int row = idx >> 4, c = idx & 15;
        const __half* src = g_wh + ((size_t)e * D_MODEL + k0 + row) * D_FF + col0 + c * 8;
        cp16(base + B_OFF + swzB(row, c), src);
    }
    cp_commit();
}

__global__ void __launch_bounds__(NTHREADS, 2)
k_gemm(const float* __restrict__ eb, float* __restrict__ out) {
    int tile = blockIdx.x;
    if (tile >= g_ntiles) return;
    int e = g_tile_expert[tile];
    int row0 = g_tile_row[tile];
    int col0 = blockIdx.y * BN;

    extern __shared__ char smem[];
    __shared__ int s_tok[BM];
    uint32_t sb = smem_u32(smem);
    int tid = threadIdx.x;
    int lane = tid & 31;
    int wid = tid >> 5;      // 8 warps
    int wm = wid & 1;        // 2 M groups (64 rows)
    int wn = wid >> 1;       // 4 N groups (32 cols)

    for (int m = tid; m < BM; m += NTHREADS) s_tok[m] = g_order[row0 + m];

    float acc[4][4][4];
#pragma unroll
    for (int a = 0; a < 4; a++)
#pragma unroll
        for (int b = 0; b < 4; b++)
#pragma unroll
            for (int c = 0; c < 4; c++) acc[a][b][c] = 0.f;

#pragma unroll
    for (int p = 0; p < PIPE - 1; p++) issue_stage(tid, sb, p, row0, e, col0, p * BK);

    int a_row = wm * 64 + (lane & 15);
    int a_cbit = (lane >> 4) & 1;
    int b_krow = lane & 15;
    int b_chalf = lane >> 4;

    for (int s = 0; s < NKSTAGE; s++) {
        cp_wait<PIPE - 2>();
        __syncthreads();
        if (s + PIPE - 1 < NKSTAGE)
            issue_stage(tid, sb, s + PIPE - 1, row0, e, col0, (s + PIPE - 1) * BK);
        else
            cp_commit();   // keep wait_group accounting aligned

        uint32_t base = sb + (s % PIPE) * STAGE_BYTES;
        uint32_t bbase = base + B_OFF;

#pragma unroll
        for (int ks = 0; ks < 4; ks++) {
            uint32_t a[4][4];
#pragma unroll
            for (int mf = 0; mf < 4; mf++)
                ldsm4(a[mf], base + A_OFF + swzA(a_row + mf * 16, ks * 2 + a_cbit));

            int krow = ks * 16 + b_krow;
#pragma unroll
            for (int t = 0; t < 2; t++) {
                int cchunk = wn * 4 + t * 2 + b_chalf;
                uint32_t bh[4];
                ldsm4t(bh, bbase + swzB(krow, cchunk));
#pragma unroll
                for (int mf = 0; mf < 4; mf++) {
                    MMA(acc[mf][t * 2],     a[mf], bh[0], bh[1]);
                    MMA(acc[mf][t * 2 + 1], a[mf], bh[2], bh[3]);
                }
            }
        }
    }
    __syncthreads();

    const float* bias = eb + (size_t)e * D_FF + col0 + wn * 32;
#pragma unroll
    for (int mf = 0; mf < 4; mf++) {
        int r_lo = wm * 64 + mf * 16 + (lane >> 2);
        int t_lo = s_tok[r_lo];
        int t_hi = s_tok[r_lo + 8];
#pragma unroll
        for (int nf = 0; nf < 4; nf++) {
            int cb = nf * 8 + (lane & 3) * 2;
            float b0 = bias[cb], b1 = bias[cb + 1];
            if (t_lo >= 0) {
                float2 v = {acc[mf][nf][0] + b0, acc[mf][nf][1] + b1};
                *(float2*)(out + (size_t)t_lo * D_FF + col0 + wn * 32 + cb) = v;
            }
            if (t_hi >= 0) {
                float2 v = {acc[mf][nf][2] + b0, acc[mf][nf][3] + b1};
                *(float2*)(out + (size_t)t_hi * D_FF + col0 + wn * 32 + cb) = v;
            }
        }
    }
}

extern "C" void kernel_launch(void* const* d_in, const int* in_sizes, int n_in,
                              void* d_out, int out_size) {
    const float* x  = (const float*)d_in[0];
    const float* gw = (const float*)d_in[1];
    const float* gb = (const float*)d_in[2];
    const float* ew = (const float*)d_in[3];
    const float* eb = (const float*)d_in[4];
    float* out = (float*)d_out;

    cudaFuncSetAttribute(k_gemm, cudaFuncAttributeMaxDynamicSharedMemorySize, SMEM_TOTAL);

    k_whalf<<<(int)(((size_t)N_EXPERTS * D_MODEL * D_FF) / (256 * 8)), 256>>>(ew);
    k_gate<<<N_TOKENS / 8, 256>>>(x, gw, gb);
    k_scan<<<1, 1>>>();
    k_scatter<<<N_TOKENS / 256, 256>>>();
    k_half_x<<<PAD_ROWS, 256>>>(x);
    {
        dim3 g(MAX_TILES, D_FF / BN);
        k_gemm<<<g, NTHREADS, SMEM_TOTAL>>>(eb, out);
    }
}

// round 14
// speedup vs baseline: 1.5984x; 1.0117x over previous
#include <cuda_runtime.h>
#include <cuda_fp16.h>
#include <cstdint>

#define N_TOKENS 8192
#define D_MODEL  1024
#define D_FF     4096
#define N_EXPERTS 8

#define BM 128
#define BN 128
#define BK 64
#define NKSTAGE (D_MODEL / BK)        // 16
#define PIPE 3
#define MAX_TILES 72
#define PAD_ROWS (N_TOKENS + N_EXPERTS * BM)   // 9216
#define NTHREADS 256

#define GATE_BLOCKS (N_TOKENS / 8)                                     // 1024
#define WHALF_BLOCKS ((int)(((size_t)N_EXPERTS * D_MODEL * D_FF) / (256 * 8)))  // 16384

// ---------------- scratch ----------------
__device__ int g_top1[N_TOKENS];
__device__ int g_counts[N_EXPERTS];
__device__ int g_cursor[N_EXPERTS];
__device__ int g_offsets[N_EXPERTS];
__device__ int g_order[PAD_ROWS];              // -1 = pad row
__device__ int g_tile_expert[MAX_TILES + 8];
__device__ int g_tile_row[MAX_TILES + 8];
__device__ int g_ntiles;

__device__ __half g_xh[(size_t)PAD_ROWS * D_MODEL];            // grouped+padded, fp16
__device__ __half g_wh[(size_t)N_EXPERTS * D_MODEL * D_FF];    // W fp16, layout [e][d][f]

// ---------------- helpers ----------------
__device__ __forceinline__ uint32_t smem_u32(const void* p) {
    uint32_t a;
    asm("{ .reg .u64 t; cvta.to.shared.u64 t, %1; cvt.u32.u64 %0, t; }" : "=r"(a) : "l"(p));
    return a;
}
__device__ __forceinline__ void cp16(uint32_t dst, const void* src) {
    asm volatile("cp.async.cg.shared.global [%0], [%1], 16;\n" :: "r"(dst), "l"(src));
}
__device__ __forceinline__ void cp_commit() { asm volatile("cp.async.commit_group;\n" ::: "memory"); }
template <int N> __device__ __forceinline__ void cp_wait() {
    asm volatile("cp.async.wait_group %0;\n" :: "n"(N) : "memory");
}
__device__ __forceinline__ void ldsm4(uint32_t r[4], uint32_t addr) {
    asm volatile("ldmatrix.sync.aligned.m8n8.x4.shared.b16 {%0,%1,%2,%3}, [%4];"
                 : "=r"(r[0]), "=r"(r[1]), "=r"(r[2]), "=r"(r[3]) : "r"(addr));
}
__device__ __forceinline__ void ldsm4t(uint32_t r[4], uint32_t addr) {
    asm volatile("ldmatrix.sync.aligned.m8n8.x4.trans.shared.b16 {%0,%1,%2,%3}, [%4];"
                 : "=r"(r[0]), "=r"(r[1]), "=r"(r[2]), "=r"(r[3]) : "r"(addr));
}
// fp16 MMA, fp32 accumulate
#define MMA(d, a, b0, b1)                                                          \
    asm volatile("mma.sync.aligned.m16n8k16.row.col.f32.f16.f16.f32 "              \
                 "{%0,%1,%2,%3},{%4,%5,%6,%7},{%8,%9},{%0,%1,%2,%3};"              \
                 : "+f"((d)[0]), "+f"((d)[1]), "+f"((d)[2]), "+f"((d)[3])          \
                 : "r"((a)[0]), "r"((a)[1]), "r"((a)[2]), "r"((a)[3]),             \
                   "r"(b0), "r"(b1))

// A tile: 128 rows x 128B (64 fp16), 8x16B chunks, chunk ^= row&7 (proven)
__device__ __forceinline__ uint32_t swzA(int row, int c) {
    return (uint32_t)(row * 128 + ((c ^ (row & 7)) << 4));
}
// B tile: 64 k-rows x 256B (128 fp16), 16x16B chunks, chunk ^= row&7 (proven)
__device__ __forceinline__ uint32_t swzB(int row, int c) {
    return (uint32_t)(row * 256 + ((c ^ (row & 7)) << 4));
}

#define A_OFF 0
#define B_OFF 16384
#define STAGE_BYTES 32768          // A 16K + B 16K
#define SMEM_TOTAL (PIPE * STAGE_BYTES)   // 98304 -> 2 CTAs/SM

// ---------------- counter zero (must precede gate atomics) ----------------
__global__ void k_zero() {
    int t = threadIdx.x;
    if (t < N_EXPERTS) { g_counts[t] = 0; g_cursor[t] = 0; }
}

// ---------------- fused prep: gate blocks [0,GATE_BLOCKS) + W convert blocks ----------------
__global__ void k_prep(const float* __restrict__ x, const float* __restrict__ gw,
                       const float* __restrict__ gb, const float* __restrict__ ew) {
    if (blockIdx.x < GATE_BLOCKS) {
        // ---- verbatim R11 gate ----
        int warp = (blockIdx.x * blockDim.x + threadIdx.x) >> 5;
        int lane = threadIdx.x & 31;
        if (warp >= N_TOKENS) return;
        const float* xr = x + (size_t)warp * D_MODEL;
        float acc[N_EXPERTS];
#pragma unroll
        for (int e = 0; e < N_EXPERTS; e++) acc[e] = 0.f;
#pragma unroll 4
        for (int i = 0; i < D_MODEL / 32; i++) {
            int d = i * 32 + lane;
            float xv = xr[d];
            const float* g = gw + d * N_EXPERTS;
#pragma unroll
            for (int e = 0; e < N_EXPERTS; e++) acc[e] += xv * g[e];
        }
#pragma unroll
        for (int e = 0; e < N_EXPERTS; e++)
#pragma unroll
            for (int off = 16; off; off >>= 1)
                acc[e] += __shfl_xor_sync(0xffffffffu, acc[e], off);
        if (lane == 0) {
            int best = 0;
            float bv = acc[0] + gb[0];
#pragma unroll
            for (int e = 1; e < N_EXPERTS; e++) {
                float v = acc[e] + gb[e];
                if (v > bv) { bv = v; best = e; }   // first max wins == jnp.argmax
            }
            g_top1[warp] = best;
            atomicAdd(&g_counts[best], 1);
        }
    } else {
        // ---- verbatim whalf convert + g_order init ----
        int gidx = (blockIdx.x - GATE_BLOCKS) * blockDim.x + threadIdx.x;
        if (gidx < PAD_ROWS) g_order[gidx] = -1;

        size_t i = (size_t)gidx * 8;
        float4 v0 = *(const float4*)(ew + i);
        float4 v1 = *(const float4*)(ew + i + 4);
        __half h[8];
        h[0] = __float2half(v0.x); h[1] = __float2half(v0.y);
        h[2] = __float2half(v0.z); h[3] = __float2half(v0.w);
        h[4] = __float2half(v1.x); h[5] = __float2half(v1.y);
        h[6] = __float2half(v1.z); h[7] = __float2half(v1.w);
        *(uint4*)(g_wh + i) = *(uint4*)h;
    }
}

__global__ void k_scan() {
    int base = 0, nt = 0;
    for (int e = 0; e < N_EXPERTS; e++) {
        g_offsets[e] = base;
        int c = g_counts[e];
        int t = (c + BM - 1) / BM;
        for (int r = 0; r < t; r++) {
            g_tile_expert[nt] = e;
            g_tile_row[nt] = base + r * BM;
            nt++;
        }
        base += t * BM;
    }
    g_ntiles = nt;
}

// ---------------- fused scatter + gather-convert (measured 13.1us in R12) ----------------
__global__ void k_scatter_convert(const float* __restrict__ x) {
    __shared__ int s_pos;
    int n = blockIdx.x;
    if (threadIdx.x == 0) {
        int e = g_top1[n];
        int pos = g_offsets[e] + atomicAdd(&g_cursor[e], 1);
        g_order[pos] = n;
        s_pos = pos;
    }
    __syncthreads();
    int pos = s_pos;
    int c0 = threadIdx.x * 4;
    float4 v = *(const float4*)(x + (size_t)n * D_MODEL + c0);
    __half h[4];
    h[0] = __float2half(v.x); h[1] = __float2half(v.y);
    h[2] = __float2half(v.z); h[3] = __float2half(v.w);
    *(uint2*)(g_xh + (size_t)pos * D_MODEL + c0) = *(uint2*)h;
    // pad rows of g_xh are written by the tail blocks below (deterministic zeros)
}

// zero the pad region of g_xh once per launch (rows claimed by no token keep zeros)
__global__ void k_zero_pad_rows() {
    // pad rows are [g_offsets[e]+count, next expert base); instead of computing,
    // rely on g_order==-1: any row not claimed keeps previous g_xh data -> must zero.
    // Cheap: zero the LAST 1024 possible pad rows' worth is wrong in general, so
    // zero rows whose g_order entry is -1.
    int row = blockIdx.x;
    if (g_order[row] != -1) return;
    int c0 = threadIdx.x * 4;
    *(uint2*)(g_xh + (size_t)row * D_MODEL + c0) = make_uint2(0u, 0u);
}

// ---------------- single-term fp16 grouped GEMM (R11/R13, unchanged) ----------------
__device__ __forceinline__ void issue_stage(int tid, uint32_t sb, int stage,
                                            int row0, int e, int col0, int k0) {
    uint32_t base = sb + (stage % PIPE) * STAGE_BYTES;
#pragma unroll
    for (int i = 0; i < 4; i++) {
        int idx = tid + i * NTHREADS;
        int row = idx >> 3, c = idx & 7;
        const __half* src = g_xh + (size_t)(row0 + row) * D_MODEL + k0 + c * 8;
        cp16(base + A_OFF + swzA(row, c), src);
    }
#pragma unroll
    for (int i = 0; i < 4; i++) {
        int idx = tid + i * NTHREADS;
        int row = idx >> 4, c = idx & 15;
        const __half* src = g_wh + ((size_t)e * D_MODEL + k0 + row) * D_FF + col0 + c * 8;
        cp16(base + B_OFF + swzB(row, c), src);
    }
    cp_commit();
}

__global__ void __launch_bounds__(NTHREADS, 2)
k_gemm(const float* __restrict__ eb, float* __restrict__ out) {
    int tile = blockIdx.x;
    if (tile >= g_ntiles) return;
    int e = g_tile_expert[tile];
    int row0 = g_tile_row[tile];
    int col0 = blockIdx.y * BN;

    extern __shared__ char smem[];
    __shared__ int s_tok[BM];
    uint32_t sb = smem_u32(smem);
    int tid = threadIdx.x;
    int lane = tid & 31;
    int wid = tid >> 5;      // 8 warps
    int wm = wid & 1;        // 2 M groups (64 rows)
    int wn = wid >> 1;       // 4 N groups (32 cols)

    for (int m = tid; m < BM; m += NTHREADS) s_tok[m] = g_order[row0 + m];

    float acc[4][4][4];
#pragma unroll
    for (int a = 0; a < 4; a++)
#pragma unroll
        for (int b = 0; b < 4; b++)
#pragma unroll
            for (int c = 0; c < 4; c++) acc[a][b][c] = 0.f;

#pragma unroll
    for (int p = 0; p < PIPE - 1; p++) issue_stage(tid, sb, p, row0, e, col0, p * BK);

    int a_row = wm * 64 + (lane & 15);
    int a_cbit = (lane >> 4) & 1;
    int b_krow = lane & 15;
    int b_chalf = lane >> 4;

    for (int s = 0; s < NKSTAGE; s++) {
        cp_wait<PIPE - 2>();
        __syncthreads();
        if (s + PIPE - 1 < NKSTAGE)
            issue_stage(tid, sb, s + PIPE - 1, row0, e, col0, (s + PIPE - 1) * BK);
        else
            cp_commit();   // keep wait_group accounting aligned

        uint32_t base = sb + (s % PIPE) * STAGE_BYTES;
        uint32_t bbase = base + B_OFF;

#pragma unroll
        for (int ks = 0; ks < 4; ks++) {
            uint32_t a[4][4];
#pragma unroll
            for (int mf = 0; mf < 4; mf++)
                ldsm4(a[mf], base + A_OFF + swzA(a_row + mf * 16, ks * 2 + a_cbit));

            int krow = ks * 16 + b_krow;
#pragma unroll
            for (int t = 0; t < 2; t++) {
                int cchunk = wn * 4 + t * 2 + b_chalf;
                uint32_t bh[4];
                ldsm4t(bh, bbase + swzB(krow, cchunk));
#pragma unroll
                for (int mf = 0; mf < 4; mf++) {
                    MMA(acc[mf][t * 2],     a[mf], bh[0], bh[1]);
                    MMA(acc[mf][t * 2 + 1], a[mf], bh[2], bh[3]);
                }
            }
        }
    }
    __syncthreads();

    const float* bias = eb + (size_t)e * D_FF + col0 + wn * 32;
#pragma unroll
    for (int mf = 0; mf < 4; mf++) {
        int r_lo = wm * 64 + mf * 16 + (lane >> 2);
        int t_lo = s_tok[r_lo];
        int t_hi = s_tok[r_lo + 8];
#pragma unroll
        for (int nf = 0; nf < 4; nf++) {
            int cb = nf * 8 + (lane & 3) * 2;
            float b0 = bias[cb], b1 = bias[cb + 1];
            if (t_lo >= 0) {
                float2 v = {acc[mf][nf][0] + b0, acc[mf][nf][1] + b1};
                *(float2*)(out + (size_t)t_lo * D_FF + col0 + wn * 32 + cb) = v;
            }
            if (t_hi >= 0) {
                float2 v = {acc[mf][nf][2] + b0, acc[mf][nf][3] + b1};
                *(float2*)(out + (size_t)t_hi * D_FF + col0 + wn * 32 + cb) = v;
            }
        }
    }
}

extern "C" void kernel_launch(void* const* d_in, const int* in_sizes, int n_in,
                              void* d_out, int out_size) {
    const float* x  = (const float*)d_in[0];
    const float* gw = (const float*)d_in[1];
    const float* gb = (const float*)d_in[2];
    const float* ew = (const float*)d_in[3];
    const float* eb = (const float*)d_in[4];
    float* out = (float*)d_out;

    cudaFuncSetAttribute(k_gemm, cudaFuncAttributeMaxDynamicSharedMemorySize, SMEM_TOTAL);

    k_zero<<<1, 32>>>();
    k_prep<<<GATE_BLOCKS + WHALF_BLOCKS, 256>>>(x, gw, gb, ew);
    k_scan<<<1, 1>>>();
    k_scatter_convert<<<N_TOKENS, 256>>>(x);
    k_zero_pad_rows<<<PAD_ROWS, 256>>>();
    {
        dim3 g(MAX_TILES, D_FF / BN);
        k_gemm<<<g, NTHREADS, SMEM_TOTAL>>>(eb, out);
    }
}

// round 15
// speedup vs baseline: 1.6285x; 1.0188x over previous
#include <cuda_runtime.h>
#include <cuda_fp16.h>
#include <cstdint>

#define N_TOKENS 8192
#define D_MODEL  1024
#define D_FF     4096
#define N_EXPERTS 8

#define BM 128
#define BN 128
#define BK 64
#define NKSTAGE (D_MODEL / BK)        // 16
#define PIPE 3
#define MAX_TILES 72
#define PAD_ROWS (N_TOKENS + N_EXPERTS * BM)   // 9216
#define NTHREADS 256

#define GATE_BLOCKS (N_TOKENS / 8)                                     // 1024
#define WHALF_BLOCKS ((int)(((size_t)N_EXPERTS * D_MODEL * D_FF) / (256 * 8)))  // 16384

// ---------------- scratch ----------------
__device__ int g_top1[N_TOKENS];
__device__ int g_counts[N_EXPERTS];
__device__ int g_cursor[N_EXPERTS];
__device__ int g_offsets[N_EXPERTS];
__device__ int g_order[PAD_ROWS];              // -1 = pad row
__device__ int g_tile_expert[MAX_TILES + 8];
__device__ int g_tile_row[MAX_TILES + 8];
__device__ int g_ntiles;

// NOTE: pad rows of g_xh may hold stale data — harmless: MMA output rows are
// independent, and the epilogue discards rows with g_order == -1.
__device__ __half g_xh[(size_t)PAD_ROWS * D_MODEL];            // grouped+padded, fp16
__device__ __half g_wh[(size_t)N_EXPERTS * D_MODEL * D_FF];    // W fp16, layout [e][d][f]

// ---------------- helpers ----------------
__device__ __forceinline__ uint32_t smem_u32(const void* p) {
    uint32_t a;
    asm("{ .reg .u64 t; cvta.to.shared.u64 t, %1; cvt.u32.u64 %0, t; }" : "=r"(a) : "l"(p));
    return a;
}
__device__ __forceinline__ void cp16(uint32_t dst, const void* src) {
    asm volatile("cp.async.cg.shared.global [%0], [%1], 16;\n" :: "r"(dst), "l"(src));
}
__device__ __forceinline__ void cp_commit() { asm volatile("cp.async.commit_group;\n" ::: "memory"); }
template <int N> __device__ __forceinline__ void cp_wait() {
    asm volatile("cp.async.wait_group %0;\n" :: "n"(N) : "memory");
}
__device__ __forceinline__ void ldsm4(uint32_t r[4], uint32_t addr) {
    asm volatile("ldmatrix.sync.aligned.m8n8.x4.shared.b16 {%0,%1,%2,%3}, [%4];"
                 : "=r"(r[0]), "=r"(r[1]), "=r"(r[2]), "=r"(r[3]) : "r"(addr));
}
__device__ __forceinline__ void ldsm4t(uint32_t r[4], uint32_t addr) {
    asm volatile("ldmatrix.sync.aligned.m8n8.x4.trans.shared.b16 {%0,%1,%2,%3}, [%4];"
                 : "=r"(r[0]), "=r"(r[1]), "=r"(r[2]), "=r"(r[3]) : "r"(addr));
}
// fp16 MMA, fp32 accumulate
#define MMA(d, a, b0, b1)                                                          \
    asm volatile("mma.sync.aligned.m16n8k16.row.col.f32.f16.f16.f32 "              \
                 "{%0,%1,%2,%3},{%4,%5,%6,%7},{%8,%9},{%0,%1,%2,%3};"              \
                 : "+f"((d)[0]), "+f"((d)[1]), "+f"((d)[2]), "+f"((d)[3])          \
                 : "r"((a)[0]), "r"((a)[1]), "r"((a)[2]), "r"((a)[3]),             \
                   "r"(b0), "r"(b1))

// A tile: 128 rows x 128B (64 fp16), 8x16B chunks, chunk ^= row&7 (proven)
__device__ __forceinline__ uint32_t swzA(int row, int c) {
    return (uint32_t)(row * 128 + ((c ^ (row & 7)) << 4));
}
// B tile: 64 k-rows x 256B (128 fp16), 16x16B chunks, chunk ^= row&7 (proven)
__device__ __forceinline__ uint32_t swzB(int row, int c) {
    return (uint32_t)(row * 256 + ((c ^ (row & 7)) << 4));
}

#define A_OFF 0
#define B_OFF 16384
#define STAGE_BYTES 32768          // A 16K + B 16K
#define SMEM_TOTAL (PIPE * STAGE_BYTES)   // 98304 -> 2 CTAs/SM

// ---------------- counter zero (must precede gate atomics) ----------------
__global__ void k_zero() {
    int t = threadIdx.x;
    if (t < N_EXPERTS) { g_counts[t] = 0; g_cursor[t] = 0; }
}

// ---------------- fused prep: gate blocks [0,GATE_BLOCKS) + W convert blocks ----------------
__global__ void k_prep(const float* __restrict__ x, const float* __restrict__ gw,
                       const float* __restrict__ gb, const float* __restrict__ ew) {
    if (blockIdx.x < GATE_BLOCKS) {
        // ---- verbatim R11 gate ----
        int warp = (blockIdx.x * blockDim.x + threadIdx.x) >> 5;
        int lane = threadIdx.x & 31;
        if (warp >= N_TOKENS) return;
        const float* xr = x + (size_t)warp * D_MODEL;
        float acc[N_EXPERTS];
#pragma unroll
        for (int e = 0; e < N_EXPERTS; e++) acc[e] = 0.f;
#pragma unroll 4
        for (int i = 0; i < D_MODEL / 32; i++) {
            int d = i * 32 + lane;
            float xv = xr[d];
            const float* g = gw + d * N_EXPERTS;
#pragma unroll
            for (int e = 0; e < N_EXPERTS; e++) acc[e] += xv * g[e];
        }
#pragma unroll
        for (int e = 0; e < N_EXPERTS; e++)
#pragma unroll
            for (int off = 16; off; off >>= 1)
                acc[e] += __shfl_xor_sync(0xffffffffu, acc[e], off);
        if (lane == 0) {
            int best = 0;
            float bv = acc[0] + gb[0];
#pragma unroll
            for (int e = 1; e < N_EXPERTS; e++) {
                float v = acc[e] + gb[e];
                if (v > bv) { bv = v; best = e; }   // first max wins == jnp.argmax
            }
            g_top1[warp] = best;
            atomicAdd(&g_counts[best], 1);
        }
    } else {
        // ---- verbatim whalf convert + g_order init ----
        int gidx = (blockIdx.x - GATE_BLOCKS) * blockDim.x + threadIdx.x;
        if (gidx < PAD_ROWS) g_order[gidx] = -1;

        size_t i = (size_t)gidx * 8;
        float4 v0 = *(const float4*)(ew + i);
        float4 v1 = *(const float4*)(ew + i + 4);
        __half h[8];
        h[0] = __float2half(v0.x); h[1] = __float2half(v0.y);
        h[2] = __float2half(v0.z); h[3] = __float2half(v0.w);
        h[4] = __float2half(v1.x); h[5] = __float2half(v1.y);
        h[6] = __float2half(v1.z); h[7] = __float2half(v1.w);
        *(uint4*)(g_wh + i) = *(uint4*)h;
    }
}

__global__ void k_scan() {
    int base = 0, nt = 0;
    for (int e = 0; e < N_EXPERTS; e++) {
        g_offsets[e] = base;
        int c = g_counts[e];
        int t = (c + BM - 1) / BM;
        for (int r = 0; r < t; r++) {
            g_tile_expert[nt] = e;
            g_tile_row[nt] = base + r * BM;
            nt++;
        }
        base += t * BM;
    }
    g_ntiles = nt;
}

// ---------------- fused scatter + gather-convert ----------------
__global__ void k_scatter_convert(const float* __restrict__ x) {
    __shared__ int s_pos;
    int n = blockIdx.x;
    if (threadIdx.x == 0) {
        int e = g_top1[n];
        int pos = g_offsets[e] + atomicAdd(&g_cursor[e], 1);
        g_order[pos] = n;
        s_pos = pos;
    }
    __syncthreads();
    int pos = s_pos;
    int c0 = threadIdx.x * 4;
    float4 v = *(const float4*)(x + (size_t)n * D_MODEL + c0);
    __half h[4];
    h[0] = __float2half(v.x); h[1] = __float2half(v.y);
    h[2] = __float2half(v.z); h[3] = __float2half(v.w);
    *(uint2*)(g_xh + (size_t)pos * D_MODEL + c0) = *(uint2*)h;
}

// ---------------- single-term fp16 grouped GEMM (R11/R13, unchanged) ----------------
__device__ __forceinline__ void issue_stage(int tid, uint32_t sb, int stage,
                                            int row0, int e, int col0, int k0) {
    uint32_t base = sb + (stage % PIPE) * STAGE_BYTES;
#pragma unroll
    for (int i = 0; i < 4; i++) {
        int idx = tid + i * NTHREADS;
        int row = idx >> 3, c = idx & 7;
        const __half* src = g_xh + (size_t)(row0 + row) * D_MODEL + k0 + c * 8;
        cp16(base + A_OFF + swzA(row, c), src);
    }
#pragma unroll
    for (int i = 0; i < 4; i++) {
        int idx = tid + i * NTHREADS;
        int row = idx >> 4, c = idx & 15;
        const __half* src = g_wh + ((size_t)e * D_MODEL + k0 + row) * D_FF + col0 + c * 8;
        cp16(base + B_OFF + swzB(row, c), src);
    }
    cp_commit();
}

__global__ void __launch_bounds__(NTHREADS, 2)
k_gemm(const float* __restrict__ eb, float* __restrict__ out) {
    int tile = blockIdx.x;
    if (tile >= g_ntiles) return;
    int e = g_tile_expert[tile];
    int row0 = g_tile_row[tile];
    int col0 = blockIdx.y * BN;

    extern __shared__ char smem[];
    __shared__ int s_tok[BM];
    uint32_t sb = smem_u32(smem);
    int tid = threadIdx.x;
    int lane = tid & 31;
    int wid = tid >> 5;      // 8 warps
    int wm = wid & 1;        // 2 M groups (64 rows)
    int wn = wid >> 1;       // 4 N groups (32 cols)

    for (int m = tid; m < BM; m += NTHREADS) s_tok[m] = g_order[row0 + m];

    float acc[4][4][4];
#pragma unroll
    for (int a = 0; a < 4; a++)
#pragma unroll
        for (int b = 0; b < 4; b++)
#pragma unroll
            for (int c = 0; c < 4; c++) acc[a][b][c] = 0.f;

#pragma unroll
    for (int p = 0; p < PIPE - 1; p++) issue_stage(tid, sb, p, row0, e, col0, p * BK);

    int a_row = wm * 64 + (lane & 15);
    int a_cbit = (lane >> 4) & 1;
    int b_krow = lane & 15;
    int b_chalf = lane >> 4;

    for (int s = 0; s < NKSTAGE; s++) {
        cp_wait<PIPE - 2>();
        __syncthreads();
        if (s + PIPE - 1 < NKSTAGE)
            issue_stage(tid, sb, s + PIPE - 1, row0, e, col0, (s + PIPE - 1) * BK);
        else
            cp_commit();   // keep wait_group accounting aligned

        uint32_t base = sb + (s % PIPE) * STAGE_BYTES;
        uint32_t bbase = base + B_OFF;

#pragma unroll
        for (int ks = 0; ks < 4; ks++) {
            uint32_t a[4][4];
#pragma unroll
            for (int mf = 0; mf < 4; mf++)
                ldsm4(a[mf], base + A_OFF + swzA(a_row + mf * 16, ks * 2 + a_cbit));

            int krow = ks * 16 + b_krow;
#pragma unroll
            for (int t = 0; t < 2; t++) {
                int cchunk = wn * 4 + t * 2 + b_chalf;
                uint32_t bh[4];
                ldsm4t(bh, bbase + swzB(krow, cchunk));
#pragma unroll
                for (int mf = 0; mf < 4; mf++) {
                    MMA(acc[mf][t * 2],     a[mf], bh[0], bh[1]);
                    MMA(acc[mf][t * 2 + 1], a[mf], bh[2], bh[3]);
                }
            }
        }
    }
    __syncthreads();

    const float* bias = eb + (size_t)e * D_FF + col0 + wn * 32;
#pragma unroll
    for (int mf = 0; mf < 4; mf++) {
        int r_lo = wm * 64 + mf * 16 + (lane >> 2);
        int t_lo = s_tok[r_lo];
        int t_hi = s_tok[r_lo + 8];
#pragma unroll
        for (int nf = 0; nf < 4; nf++) {
            int cb = nf * 8 + (lane & 3) * 2;
            float b0 = bias[cb], b1 = bias[cb + 1];
            if (t_lo >= 0) {
                float2 v = {acc[mf][nf][0] + b0, acc[mf][nf][1] + b1};
                *(float2*)(out + (size_t)t_lo * D_FF + col0 + wn * 32 + cb) = v;
            }
            if (t_hi >= 0) {
                float2 v = {acc[mf][nf][2] + b0, acc[mf][nf][3] + b1};
                *(float2*)(out + (size_t)t_hi * D_FF + col0 + wn * 32 + cb) = v;
            }
        }
    }
}

extern "C" void kernel_launch(void* const* d_in, const int* in_sizes, int n_in,
                              void* d_out, int out_size) {
    const float* x  = (const float*)d_in[0];
    const float* gw = (const float*)d_in[1];
    const float* gb = (const float*)d_in[2];
    const float* ew = (const float*)d_in[3];
    const float* eb = (const float*)d_in[4];
    float* out = (float*)d_out;

    cudaFuncSetAttribute(k_gemm, cudaFuncAttributeMaxDynamicSharedMemorySize, SMEM_TOTAL);

    k_zero<<<1, 32>>>();
    k_prep<<<GATE_BLOCKS + WHALF_BLOCKS, 256>>>(x, gw, gb, ew);
    k_scan<<<1, 1>>>();
    k_scatter_convert<<<N_TOKENS, 256>>>(x);
    {
        dim3 g(MAX_TILES, D_FF / BN);
        k_gemm<<<g, NTHREADS, SMEM_TOTAL>>>(eb, out);
    }
}